// round 3
// baseline (speedup 1.0000x reference)
#include <cuda_runtime.h>

#define N_MAX   1000000
#define D       32
#define HID     16
#define NB      592          // grid for K1/K3
#define T1      128

// ---------------- scratch (no allocations allowed) ----------------
__device__ float g_a[N_MAX];          // per-row raw attention logits
__device__ float g_bm[NB];            // per-block running max
__device__ float g_bs[NB];            // per-block running sumexp
__device__ float g_bB[NB * D];        // per-block partial alpha-weighted H
__device__ float g_stats[2];          // [0]=global max, [1]=1/S
__device__ unsigned int g_cnt1;       // zero-initialized; reset after each use
__device__ unsigned int g_cnt3;

// ---------------- packed f32x2 helpers ----------------
__device__ __forceinline__ unsigned long long pack2(float lo, float hi) {
    unsigned long long r;
    asm("mov.b64 %0, {%1, %2};" : "=l"(r) : "f"(lo), "f"(hi));
    return r;
}
__device__ __forceinline__ void unpack2(unsigned long long v, float& lo, float& hi) {
    asm("mov.b64 {%0, %1}, %2;" : "=f"(lo), "=f"(hi) : "l"(v));
}
__device__ __forceinline__ void fma2(unsigned long long& d,
                                     unsigned long long a, unsigned long long b) {
    asm("fma.rn.f32x2 %0, %1, %2, %3;" : "=l"(d) : "l"(a), "l"(b), "l"(d));
}
__device__ __forceinline__ float fast_tanh(float x) {
    float r;
    asm("tanh.approx.f32 %0, %1;" : "=f"(r) : "f"(x));
    return r;
}

// =====================================================================
// K1: per-row logits + per-block (max,sumexp); last block folds in the
//     global-stats combine (old K2).  NO forced occupancy -> no reg cap
//     -> no spills (R1/R2 root cause).
// =====================================================================
__global__ void __launch_bounds__(T1)
k1_logits(const float4* __restrict__ H4, int n,
          const float* __restrict__ Wv, const float* __restrict__ bv,
          const float* __restrict__ Wu, const float* __restrict__ bu,
          const float* __restrict__ Ww, const float* __restrict__ bw)
{
    // sw[d][0..15] = Wv[d][:], sw[d][16..31] = Wu[d][:]  (128B rows)
    __shared__ __align__(16) float sw[D][32];
    __shared__ float sbv[HID], sbu[HID], sWw[HID];
    __shared__ float red_m[T1], red_s[T1];
    __shared__ bool  isLast;

    const int t = threadIdx.x;
    for (int i = t; i < D * HID; i += T1) {
        sw[i / HID][i % HID]       = Wv[i];
        sw[i / HID][16 + i % HID]  = Wu[i];
    }
    if (t < HID) { sbv[t] = bv[t]; sbu[t] = bu[t]; sWw[t] = Ww[t]; }
    __syncthreads();

    const float bw0 = bw[0];
    float m = -1e30f, s = 0.0f;

    for (int r = blockIdx.x * T1 + t; r < n; r += NB * T1) {
        const float4* p = H4 + (size_t)r * 8;

        unsigned long long v[HID / 2], u[HID / 2];
        #pragma unroll
        for (int k = 0; k < HID / 2; k++) { v[k] = 0ULL; u[k] = 0ULL; }

        #pragma unroll
        for (int c = 0; c < 8; c++) {
            float4 x = p[c];                       // chunked: low live-reg count
            float xv[4] = {x.x, x.y, x.z, x.w};
            #pragma unroll
            for (int j = 0; j < 4; j++) {
                const int d = c * 4 + j;
                const unsigned long long hd = pack2(xv[j], xv[j]);
                const ulonglong2* w2 = (const ulonglong2*)sw[d];
                #pragma unroll
                for (int k = 0; k < 4; k++) {      // Wv half
                    ulonglong2 w = w2[k];
                    fma2(v[2 * k], hd, w.x);
                    fma2(v[2 * k + 1], hd, w.y);
                }
                #pragma unroll
                for (int k = 0; k < 4; k++) {      // Wu half
                    ulonglong2 w = w2[4 + k];
                    fma2(u[2 * k], hd, w.x);
                    fma2(u[2 * k + 1], hd, w.y);
                }
            }
        }

        float a = bw0;
        #pragma unroll
        for (int k = 0; k < HID / 2; k++) {
            float v0, v1, u0, u1;
            unpack2(v[k], v0, v1);
            unpack2(u[k], u0, u1);
            const int h0 = 2 * k, h1 = 2 * k + 1;
            float t0 = fast_tanh(v0 + sbv[h0]);
            float t1 = fast_tanh(v1 + sbv[h1]);
            float s0 = fmaf(0.5f, fast_tanh(0.5f * (u0 + sbu[h0])), 0.5f);
            float s1 = fmaf(0.5f, fast_tanh(0.5f * (u1 + sbu[h1])), 0.5f);
            a = fmaf(sWw[h0] * t0, s0, a);
            a = fmaf(sWw[h1] * t1, s1, a);
        }
        g_a[r] = a;

        float mn = fmaxf(m, a);
        s = fmaf(s, __expf(m - mn), __expf(a - mn));
        m = mn;
    }

    // block reduction of (m, s)
    red_m[t] = m; red_s[t] = s;
    for (int stride = T1 / 2; stride >= 1; stride >>= 1) {
        __syncthreads();
        if (t < stride) {
            float m1 = red_m[t], s1 = red_s[t];
            float m2 = red_m[t + stride], s2 = red_s[t + stride];
            float mn = fmaxf(m1, m2);
            red_m[t] = mn;
            red_s[t] = fmaf(s1, __expf(m1 - mn), s2 * __expf(m2 - mn));
        }
    }
    __syncthreads();
    if (t == 0) { g_bm[blockIdx.x] = red_m[0]; g_bs[blockIdx.x] = red_s[0]; }

    // -------- last finishing block computes global (gm, 1/S) --------
    __threadfence();
    if (t == 0) isLast = (atomicAdd(&g_cnt1, 1u) == NB - 1);
    __syncthreads();
    if (!isLast) return;

    float lm = -1e30f, ls = 0.0f;
    for (int b = t; b < NB; b += T1) {
        float mb = g_bm[b], sb = g_bs[b];
        float mn = fmaxf(lm, mb);
        ls = fmaf(ls, __expf(lm - mn), sb * __expf(mb - mn));
        lm = mn;
    }
    red_m[t] = lm; red_s[t] = ls;
    for (int stride = T1 / 2; stride >= 1; stride >>= 1) {
        __syncthreads();
        if (t < stride) {
            float m1 = red_m[t], s1 = red_s[t];
            float m2 = red_m[t + stride], s2 = red_s[t + stride];
            float mn = fmaxf(m1, m2);
            red_m[t] = mn;
            red_s[t] = fmaf(s1, __expf(m1 - mn), s2 * __expf(m2 - mn));
        }
    }
    __syncthreads();
    if (t == 0) {
        g_stats[0] = red_m[0];
        g_stats[1] = 1.0f / red_s[0];
        g_cnt1 = 0;                     // reset for next graph replay
        __threadfence();
    }
}

// =====================================================================
// K3: alpha_i = exp(a_i - gm)*invS (written out) + per-block partial
//     B = sum alpha_i * H_i ; last block folds in Bbar + score head.
// =====================================================================
__global__ void __launch_bounds__(T1)
k3_alpha_B(const float4* __restrict__ H4, int n, float* __restrict__ alpha,
           const float* __restrict__ TPL,
           const float* __restrict__ W1, const float* __restrict__ b1,
           const float* __restrict__ W2, const float* __restrict__ b2,
           float* __restrict__ out_score)
{
    __shared__ float redB[T1][D];       // 16 KB
    __shared__ bool  isLast;
    const int t = threadIdx.x;
    const float gm = g_stats[0], invS = g_stats[1];

    unsigned long long B[D / 2];
    #pragma unroll
    for (int k = 0; k < D / 2; k++) B[k] = 0ULL;

    for (int r = blockIdx.x * T1 + t; r < n; r += NB * T1) {
        const float4* p = H4 + (size_t)r * 8;
        float e = __expf(g_a[r] - gm) * invS;
        alpha[r] = e;
        const unsigned long long ee = pack2(e, e);
        #pragma unroll
        for (int c = 0; c < 8; c++) {
            float4 x = p[c];
            fma2(B[2 * c],     ee, pack2(x.x, x.y));
            fma2(B[2 * c + 1], ee, pack2(x.z, x.w));
        }
    }

    #pragma unroll
    for (int k = 0; k < D / 2; k++) {
        float lo, hi;
        unpack2(B[k], lo, hi);
        redB[t][2 * k] = lo; redB[t][2 * k + 1] = hi;
    }
    __syncthreads();
    if (t < D) {
        float acc = 0.0f;
        #pragma unroll 8
        for (int i = 0; i < T1; i++) acc += redB[i][t];
        g_bB[blockIdx.x * D + t] = acc;
    }

    // -------- last finishing block: Bbar + score head --------
    __threadfence();
    if (t == 0) isLast = (atomicAdd(&g_cnt3, 1u) == NB - 1);
    __syncthreads();
    if (!isLast) return;

    // reduce g_bB columns: 4 groups of 32 lanes
    const int d = t & (D - 1);
    const int g = t >> 5;               // 0..3
    float acc = 0.0f;
    for (int b = g; b < NB; b += 4) acc += g_bB[b * D + d];
    redB[g][d] = acc;
    __syncthreads();

    __shared__ float Bbar[D];
    __shared__ float hsh[HID];
    if (t < D) Bbar[t] = redB[0][t] + redB[1][t] + redB[2][t] + redB[3][t];
    __syncthreads();
    if (t < HID) {
        float a3 = b1[t] + TPL[0] * W1[D * HID + t];    // W1 row 32 = TPL row
        #pragma unroll
        for (int dd = 0; dd < D; dd++) a3 = fmaf(Bbar[dd], W1[dd * HID + t], a3);
        hsh[t] = fmaxf(a3, 0.0f);
    }
    __syncthreads();
    if (t == 0) {
        float sc = b2[0];
        #pragma unroll
        for (int j = 0; j < HID; j++) sc = fmaf(hsh[j], W2[j], sc);
        out_score[0] = sc;
        g_cnt3 = 0;                     // reset for next graph replay
        __threadfence();
    }
}

// =====================================================================
// Inputs (metadata order): H, TPL, Wv, bv, Wu, bu, Ww, bw, W1, b1, W2, b2
// Output: [score, alpha[0..N-1]]
// =====================================================================
extern "C" void kernel_launch(void* const* d_in, const int* in_sizes, int n_in,
                              void* d_out, int out_size)
{
    const float* H   = (const float*)d_in[0];
    const float* TPL = (const float*)d_in[1];
    const float* Wv  = (const float*)d_in[2];
    const float* bv  = (const float*)d_in[3];
    const float* Wu  = (const float*)d_in[4];
    const float* bu  = (const float*)d_in[5];
    const float* Ww  = (const float*)d_in[6];
    const float* bw  = (const float*)d_in[7];
    const float* W1  = (const float*)d_in[8];
    const float* b1  = (const float*)d_in[9];
    const float* W2  = (const float*)d_in[10];
    const float* b2  = (const float*)d_in[11];
    float* out = (float*)d_out;

    const int n = in_sizes[0] / D;   // 1,000,000

    k1_logits<<<NB, T1>>>((const float4*)H, n, Wv, bv, Wu, bu, Ww, bw);
    k3_alpha_B<<<NB, T1>>>((const float4*)H, n, out + 1,
                           TPL, W1, b1, W2, b2, out);
}

// round 6
// speedup vs baseline: 1.9403x; 1.9403x over previous
#include <cuda_runtime.h>

#define N_MAX   1000000
#define D       32
#define HID     16
#define NB      592          // 148 SMs x 4 blocks
#define T1      128

// ---------------- scratch (no allocations allowed) ----------------
__device__ float g_a[N_MAX];          // per-row raw attention logits
__device__ float g_bs[NB];            // per-block sum of exp(a)
__device__ float g_bB[NB * D];        // per-block partial sum exp(a)*H
__device__ float g_invS;              // 1 / sum exp(a)
__device__ unsigned int g_cnt1;       // zero-init; reset each replay

// ---------------- packed f32x2 helpers ----------------
__device__ __forceinline__ unsigned long long pack2(float lo, float hi) {
    unsigned long long r;
    asm("mov.b64 %0, {%1, %2};" : "=l"(r) : "f"(lo), "f"(hi));
    return r;
}
__device__ __forceinline__ void unpack2(unsigned long long v, float& lo, float& hi) {
    asm("mov.b64 {%0, %1}, %2;" : "=f"(lo), "=f"(hi) : "l"(v));
}
__device__ __forceinline__ void fma2(unsigned long long& d,
                                     unsigned long long a, unsigned long long b) {
    asm("fma.rn.f32x2 %0, %1, %2, %3;" : "=l"(d) : "l"(a), "l"(b), "l"(d));
}
__device__ __forceinline__ float fast_tanh(float x) {
    float r;
    asm("tanh.approx.f32 %0, %1;" : "=f"(r) : "f"(x));
    return r;
}

// =====================================================================
// K1: single pass over H.
//   a_i -> g_a ;  s += exp(a_i) ;  B += exp(a_i) * H_i   (row in regs)
// exp without max-shift is safe: |a| <= |bw| + sum|Ww| ~ 10.
// Front-batched 8x LDG.128 (MLP=8): R3 measured MLP=1 costs 10x.
// No occupancy clause: R1/R2 measured the reg cap causes spill traffic.
// Last finishing block folds in: S, Bbar = B/S, and the score head.
// =====================================================================
__global__ void __launch_bounds__(T1)
k1_fused(const float4* __restrict__ H4, int n,
         const float* __restrict__ Wv, const float* __restrict__ bv,
         const float* __restrict__ Wu, const float* __restrict__ bu,
         const float* __restrict__ Ww, const float* __restrict__ bw,
         const float* __restrict__ TPL,
         const float* __restrict__ W1, const float* __restrict__ b1,
         const float* __restrict__ W2, const float* __restrict__ b2,
         float* __restrict__ out_score)
{
    // sw[d][0..15] = Wv[d][:],  sw[d][16..31] = Wu[d][:]
    __shared__ __align__(16) float sw[D][32];
    __shared__ float sbv[HID], sbu[HID], sWw[HID];
    __shared__ float red_s[T1];
    __shared__ float redB[T1][D];          // 16 KB
    __shared__ bool  isLast;

    const int t = threadIdx.x;
    for (int i = t; i < D * HID; i += T1) {
        sw[i / HID][i % HID]      = Wv[i];
        sw[i / HID][16 + i % HID] = Wu[i];
    }
    if (t < HID) { sbv[t] = bv[t]; sbu[t] = bu[t]; sWw[t] = Ww[t]; }
    __syncthreads();

    const float bw0 = bw[0];
    float s = 0.0f;

    unsigned long long B[D / 2];
    #pragma unroll
    for (int k = 0; k < D / 2; k++) B[k] = 0ULL;

    #pragma unroll 1
    for (int r = blockIdx.x * T1 + t; r < n; r += NB * T1) {
        // ---- front-batched row load: 8 independent LDG.128 (MLP=8) ----
        const float4* p = H4 + (size_t)r * 8;
        float4 x[8];
        #pragma unroll
        for (int c = 0; c < 8; c++) x[c] = p[c];

        unsigned long long v[HID / 2], u[HID / 2];
        #pragma unroll
        for (int k = 0; k < HID / 2; k++) { v[k] = 0ULL; u[k] = 0ULL; }

        #pragma unroll
        for (int c = 0; c < 8; c++) {
            #pragma unroll
            for (int j = 0; j < 4; j++) {
                const float xj = (j == 0) ? x[c].x : (j == 1) ? x[c].y
                               : (j == 2) ? x[c].z : x[c].w;
                const unsigned long long hd = pack2(xj, xj);
                const ulonglong2* w2 = (const ulonglong2*)sw[c * 4 + j];
                #pragma unroll
                for (int k = 0; k < 4; k++) {          // Wv half
                    ulonglong2 w = w2[k];
                    fma2(v[2 * k], hd, w.x);
                    fma2(v[2 * k + 1], hd, w.y);
                }
                #pragma unroll
                for (int k = 0; k < 4; k++) {          // Wu half
                    ulonglong2 w = w2[4 + k];
                    fma2(u[2 * k], hd, w.x);
                    fma2(u[2 * k + 1], hd, w.y);
                }
            }
        }

        float a = bw0;
        #pragma unroll
        for (int k = 0; k < HID / 2; k++) {
            float v0, v1, u0, u1;
            unpack2(v[k], v0, v1);
            unpack2(u[k], u0, u1);
            const int h0 = 2 * k, h1 = 2 * k + 1;
            float t0 = fast_tanh(v0 + sbv[h0]);
            float t1 = fast_tanh(v1 + sbv[h1]);
            float s0 = fmaf(0.5f, fast_tanh(0.5f * (u0 + sbu[h0])), 0.5f);
            float s1 = fmaf(0.5f, fast_tanh(0.5f * (u1 + sbu[h1])), 0.5f);
            a = fmaf(sWw[h0] * t0, s0, a);
            a = fmaf(sWw[h1] * t1, s1, a);
        }
        g_a[r] = a;

        const float e = __expf(a);             // |a| bounded -> safe
        s += e;
        const unsigned long long ee = pack2(e, e);
        #pragma unroll
        for (int c = 0; c < 8; c++) {
            fma2(B[2 * c],     ee, pack2(x[c].x, x[c].y));
            fma2(B[2 * c + 1], ee, pack2(x[c].z, x[c].w));
        }
    }

    // ---- block reduction: s and B ----
    red_s[t] = s;
    #pragma unroll
    for (int k = 0; k < D / 2; k++) {
        float lo, hi;
        unpack2(B[k], lo, hi);
        redB[t][2 * k] = lo; redB[t][2 * k + 1] = hi;
    }
    for (int stride = T1 / 2; stride >= 1; stride >>= 1) {
        __syncthreads();
        if (t < stride) red_s[t] += red_s[t + stride];
    }
    __syncthreads();
    if (t == 0) g_bs[blockIdx.x] = red_s[0];
    if (t < D) {
        float acc = 0.0f;
        for (int i = 0; i < T1; i++) acc += redB[i][t];
        g_bB[blockIdx.x * D + t] = acc;
    }

    // ---- last finishing block: S, Bbar, score head ----
    __threadfence();
    if (t == 0) isLast = (atomicAdd(&g_cnt1, 1u) == NB - 1);
    __syncthreads();
    if (!isLast) return;

    float ls = 0.0f;
    for (int b = t; b < NB; b += T1) ls += g_bs[b];
    red_s[t] = ls;
    for (int stride = T1 / 2; stride >= 1; stride >>= 1) {
        __syncthreads();
        if (t < stride) red_s[t] += red_s[t + stride];
    }
    __syncthreads();
    const float S = red_s[0];
    if (t == 0) g_invS = 1.0f / S;

    // Bbar: 4 groups of 32 lanes over blocks
    {
        const int d = t & (D - 1);
        const int g = t >> 5;                  // 0..3
        float acc = 0.0f;
        for (int b = g; b < NB; b += 4) acc += g_bB[b * D + d];
        redB[g][d] = acc;
    }
    __syncthreads();

    __shared__ float Bbar[D];
    __shared__ float hsh[HID];
    if (t < D) Bbar[t] = (redB[0][t] + redB[1][t] + redB[2][t] + redB[3][t]) / S;
    __syncthreads();
    if (t < HID) {
        float a3 = b1[t] + TPL[0] * W1[D * HID + t];   // W1 row 32 = TPL row
        #pragma unroll
        for (int dd = 0; dd < D; dd++) a3 = fmaf(Bbar[dd], W1[dd * HID + t], a3);
        hsh[t] = fmaxf(a3, 0.0f);
    }
    __syncthreads();
    if (t == 0) {
        float sc = b2[0];
        #pragma unroll
        for (int j = 0; j < HID; j++) sc = fmaf(hsh[j], W2[j], sc);
        out_score[0] = sc;
        g_cnt1 = 0;                            // reset for next graph replay
        __threadfence();
    }
}

// =====================================================================
// K2: alpha_i = exp(a_i) * invS   (pure 8 MB stream)
// =====================================================================
__global__ void __launch_bounds__(256)
k2_alpha(float* __restrict__ alpha, int n)
{
    const float inv = g_invS;
    int i = blockIdx.x * blockDim.x + threadIdx.x;
    if (i < n) alpha[i] = __expf(g_a[i]) * inv;
}

// =====================================================================
// Inputs (metadata order): H, TPL, Wv, bv, Wu, bu, Ww, bw, W1, b1, W2, b2
// Output: [score, alpha[0..N-1]]
// =====================================================================
extern "C" void kernel_launch(void* const* d_in, const int* in_sizes, int n_in,
                              void* d_out, int out_size)
{
    const float* H   = (const float*)d_in[0];
    const float* TPL = (const float*)d_in[1];
    const float* Wv  = (const float*)d_in[2];
    const float* bv  = (const float*)d_in[3];
    const float* Wu  = (const float*)d_in[4];
    const float* bu  = (const float*)d_in[5];
    const float* Ww  = (const float*)d_in[6];
    const float* bw  = (const float*)d_in[7];
    const float* W1  = (const float*)d_in[8];
    const float* b1  = (const float*)d_in[9];
    const float* W2  = (const float*)d_in[10];
    const float* b2  = (const float*)d_in[11];
    float* out = (float*)d_out;

    const int n = in_sizes[0] / D;   // 1,000,000

    k1_fused<<<NB, T1>>>((const float4*)H, n, Wv, bv, Wu, bu, Ww, bw,
                         TPL, W1, b1, W2, b2, out);
    k2_alpha<<<(n + 255) / 256, 256>>>(out + 1, n);
}